// round 7
// baseline (speedup 1.0000x reference)
#include <cuda_runtime.h>

#define XS   8192
#define NBLK 128

// Scratch (allocation-free)
__device__ float4 g_wdT4[16 * 256];                   // [k][o*8+iq]
__device__ float  g_Tpart[8 * 2 * 32 * 16 * 32];      // [Bg][pq][s][k][o]
__device__ unsigned int g_cnt2[4];                    // per k-quad

__device__ __forceinline__ unsigned int ld_acq(const unsigned int* p) {
    unsigned int v;
    asm volatile("ld.acquire.gpu.u32 %0, [%1];" : "=r"(v) : "l"(p));
    return v;
}

__device__ __forceinline__ float4 shfl_xor_add_f4(float4 v, int d) {
    float4 r;
    r.x = v.x + __shfl_xor_sync(0xffffffffu, v.x, d);
    r.y = v.y + __shfl_xor_sync(0xffffffffu, v.y, d);
    r.z = v.z + __shfl_xor_sync(0xffffffffu, v.z, d);
    r.w = v.w + __shfl_xor_sync(0xffffffffu, v.w, d);
    return r;
}

__global__ void __launch_bounds__(512, 1) fused_kernel(
    const float* __restrict__ x,
    const float* __restrict__ w_diag,
    const float* __restrict__ w_off,
    const float* __restrict__ b1,
    const int*   __restrict__ perm,
    float*       __restrict__ out)
{
    // f4 union: Wp[0,544) Wm[544,1088) Sp[1088,1632) Sm[1632,2176)
    // reused as: stage floats [0,8208);  phase-2 wdsh4 [0,1056)
    __shared__ float4 SM4[2176];
    __shared__ float  tsh[256];
    __shared__ float  bsh[32];
    float* SMf = (float*)SM4;

    const int b = blockIdx.x, t = threadIdx.x;
    const int k1 = b >> 3, Bg = b & 7;        // phase-1 role
    const int s2 = b >> 2, kq = b & 3;        // phase-2 role

    if (t < 32) bsh[t] = __ldg(&b1[t]);

    // phase-2 indices (early)
    const int kk  = t >> 7;
    const int aa  = (t >> 3) & 15;
    const int og2 = t & 7;
    const int n2  = __ldg(&perm[kq * 64 + kk * 16 + aa]);

    // ---- W prefetch for contraction ----
    const float4* woff4 = (const float4*)w_off;     // [c][k][B/4]
    float4 wreg[2];
#pragma unroll
    for (int j = 0; j < 2; j++)
        wreg[j] = __ldg(&woff4[(j * 512 + t) * 128 + k1 * 8 + Bg]);

    // ---- w_diag transpose (one block per k), covered by cnt2 fence ----
    if (Bg == 0) {
        float* gw = (float*)g_wdT4;
#pragma unroll
        for (int j = 0; j < 2; j++) {
            int c = j * 512 + t;
            gw[k1 * 1024 + c] = __ldg(&w_diag[c * 16 + k1]);
        }
    }

    // ================= phase A: local gather + S± pooling ===================
    {
        const int sA = t >> 4, iqA = t & 7, rh = (t >> 3) & 1;
        const float4* x4 = (const float4*)x;
        float4 sB[4];
#pragma unroll
        for (int Bl = 0; Bl < 4; Bl++) {
            float4 a = make_float4(0.f, 0.f, 0.f, 0.f);
#pragma unroll
            for (int rr = 0; rr < 4; rr++) {
                int n = __ldg(&perm[Bg * 32 + Bl * 8 + rh * 4 + rr]);
                float4 v = __ldg(&x4[sA * 2048 + n * 8 + iqA]);
                a.x += v.x; a.y += v.y; a.z += v.z; a.w += v.w;
            }
            sB[Bl] = a;
        }
#pragma unroll
        for (int Bl = 0; Bl < 4; Bl++) sB[Bl] = shfl_xor_add_f4(sB[Bl], 8);

        if (rh == 0) {   // Sp rows: [s*17 + m*8 + iq]
            float4 p0, p1;
            p0.x = sB[0].x + sB[1].x; p0.y = sB[0].y + sB[1].y;
            p0.z = sB[0].z + sB[1].z; p0.w = sB[0].w + sB[1].w;
            p1.x = sB[2].x + sB[3].x; p1.y = sB[2].y + sB[3].y;
            p1.z = sB[2].z + sB[3].z; p1.w = sB[2].w + sB[3].w;
            SM4[1088 + sA * 17 +     iqA] = p0;
            SM4[1088 + sA * 17 + 8 + iqA] = p1;
        } else {         // Sm rows
            float4 q0, q1;
            q0.x = sB[0].x - sB[1].x; q0.y = sB[0].y - sB[1].y;
            q0.z = sB[0].z - sB[1].z; q0.w = sB[0].w - sB[1].w;
            q1.x = sB[2].x - sB[3].x; q1.y = sB[2].y - sB[3].y;
            q1.z = sB[2].z - sB[3].z; q1.w = sB[2].w - sB[3].w;
            SM4[1632 + sA * 17 +     iqA] = q0;
            SM4[1632 + sA * 17 + 8 + iqA] = q1;
        }
    }

    // ---- W± -> smem ----
    {
        float* Wp = SMf;              // row o: 68 floats
        float* Wm = SMf + 544 * 4;
#pragma unroll
        for (int jj = 0; jj < 2; jj++) {
            int c = jj * 512 + t, o = c >> 5, i = c & 31;
            float4 w = wreg[jj];
            Wp[o * 68 +      i] = w.x + w.y;   // m=0
            Wp[o * 68 + 32 + i] = w.z + w.w;   // m=1
            Wm[o * 68 +      i] = w.x - w.y;
            Wm[o * 68 + 32 + i] = w.z - w.w;
        }
    }
    __syncthreads();

    // ================= phase B: contraction (all 512 threads) ===============
    float acc[4][4];
    {
        const int pq = t >> 8, sh = (t >> 5) & 7, og = (t >> 2) & 7, ih = t & 3;
        const float4* Wb = SM4 + (pq ? 544 : 0);
        const float4* Sb = SM4 + 1088 + (pq ? 544 : 0);
#pragma unroll
        for (int j = 0; j < 16; j++) ((float*)acc)[j] = 0.f;
#pragma unroll
        for (int m = 0; m < 2; m++)
#pragma unroll
            for (int j = 0; j < 2; j++) {
                int iq = ih * 2 + j;
                float4 s4[4], w4[4];
#pragma unroll
                for (int ss = 0; ss < 4; ss++)
                    s4[ss] = Sb[(sh + 8 * ss) * 17 + m * 8 + iq];
#pragma unroll
                for (int oo = 0; oo < 4; oo++)
                    w4[oo] = Wb[(og + 8 * oo) * 17 + m * 8 + iq];
#pragma unroll
                for (int ss = 0; ss < 4; ss++)
#pragma unroll
                    for (int oo = 0; oo < 4; oo++)
                        acc[ss][oo] += w4[oo].x * s4[ss].x + w4[oo].y * s4[ss].y
                                     + w4[oo].z * s4[ss].z + w4[oo].w * s4[ss].w;
            }
    }
    __syncthreads();
    // stage: [j][t] rows of 513 floats (conflict-free both directions)
#pragma unroll
    for (int jj = 0; jj < 16; jj++)
        SMf[jj * 513 + t] = acc[jj >> 2][jj & 3];
    __syncthreads();
    // reduce over ih (4) and store Tpart (coalesced over o)
    {
        const int pq = t >> 8, sh = (t >> 5) & 7, oo = (t >> 3) & 3, og = t & 7;
        const int g = pq * 64 + sh * 8 + og;
#pragma unroll
        for (int ss = 0; ss < 4; ss++) {
            int j = ss * 4 + oo;
            float v = SMf[j * 513 + g * 4 + 0] + SMf[j * 513 + g * 4 + 1]
                    + SMf[j * 513 + g * 4 + 2] + SMf[j * 513 + g * 4 + 3];
            g_Tpart[((Bg * 2 + pq) * 32 + (sh + 8 * ss)) * 512 + k1 * 32
                    + (og + 8 * oo)] = v;
        }
    }

    // ---- sync: wait for the 32 producers of k-quad kq; pre-issue x gathers --
    __threadfence();
    __syncthreads();
    unsigned int tgt2 = 0;
    if (t == 0) {
        unsigned int my = atomicAdd(&g_cnt2[b >> 5], 1u);
        tgt2 = ((my >> 5) + 1u) << 5;
    }
    float4 xr[8];
    {
        const float4* xrow = (const float4*)(x + s2 * XS + n2 * 32);
#pragma unroll
        for (int iq = 0; iq < 8; iq++) xr[iq] = __ldg(&xrow[iq]);
    }
    if (t == 0) { while (ld_acq(&g_cnt2[kq]) < tgt2) {} }
    __syncthreads();

    // ================= phase C: finalize =================
    float4* wdsh4 = SM4;   // [(kk*8+iq)*33 + o]
#pragma unroll
    for (int j = 0; j < 2; j++) {
        int e = j * 512 + t;
        int kkk = e >> 8, o2 = (e >> 3) & 31, iqq = e & 7;
        wdsh4[(kkk * 8 + iqq) * 33 + o2] = __ldcg(&g_wdT4[(kq * 4 + kkk) * 256 + (e & 255)]);
    }
    if (t < 256) {
        int kk0 = t >> 6, p = (t >> 5) & 1, o0 = t & 31;
        int k = kq * 4 + kk0;
        float P = 0.f, Q = 0.f;
#pragma unroll
        for (int Bg2 = 0; Bg2 < 8; Bg2++) {
            P += __ldcg(&g_Tpart[((Bg2 * 2 + 0) * 32 + s2) * 512 + k * 32 + o0]);
            Q += __ldcg(&g_Tpart[((Bg2 * 2 + 1) * 32 + s2) * 512 + k * 32 + o0]);
        }
        tsh[t] = (p ? (P - Q) : (P + Q)) * (1.0f / 512.0f);
    }
    __syncthreads();

    const int pa = aa >> 3;
    float acc2[4];
#pragma unroll
    for (int oo = 0; oo < 4; oo++)
        acc2[oo] = tsh[kk * 64 + pa * 32 + og2 + 8 * oo] + bsh[og2 + 8 * oo];
#pragma unroll
    for (int iq = 0; iq < 8; iq++) {
        float4 xv = xr[iq];
#pragma unroll
        for (int oo = 0; oo < 4; oo++) {
            float4 wv = wdsh4[(kk * 8 + iq) * 33 + og2 + 8 * oo];
            acc2[oo] += wv.x * xv.x + wv.y * xv.y + wv.z * xv.z + wv.w * xv.w;
        }
    }
    float* orow = out + s2 * XS + n2 * 32;
#pragma unroll
    for (int oo = 0; oo < 4; oo++) orow[og2 + 8 * oo] = acc2[oo];
}

// ---------------------------------------------------------------------------
extern "C" void kernel_launch(void* const* d_in, const int* in_sizes, int n_in,
                              void* d_out, int out_size)
{
    const float* x      = (const float*)d_in[0];
    const float* w_diag = (const float*)d_in[1];
    const float* w_off  = (const float*)d_in[2];
    const float* b1     = (const float*)d_in[3];
    const int*   perm   = (const int*)d_in[4];
    float* out = (float*)d_out;

    fused_kernel<<<NBLK, 512>>>(x, w_diag, w_off, b1, perm, out);
}

// round 8
// speedup vs baseline: 1.2455x; 1.2455x over previous
#include <cuda_runtime.h>

#define XS   8192
#define NBLK 128

// Scratch (allocation-free)
__device__ float g_Tpart[16 * 8 * 2 * 1024];   // [k][Bg][pq][s][o]
__device__ unsigned int g_cnt[16];             // per-k counters (8 producers each)

static __device__ __forceinline__ unsigned int ld_acq(const unsigned int* p) {
    unsigned int v;
    asm volatile("ld.acquire.gpu.u32 %0, [%1];" : "=r"(v) : "l"(p));
    return v;
}
static __device__ __forceinline__ unsigned int atom_add_rel(unsigned int* p, unsigned int v) {
    unsigned int o;
    asm volatile("atom.release.gpu.add.u32 %0, [%1], %2;"
                 : "=r"(o) : "l"(p), "r"(v) : "memory");
    return o;
}

__device__ __forceinline__ float4 shfl_xor_add_f4(float4 v, int d) {
    float4 r;
    r.x = v.x + __shfl_xor_sync(0xffffffffu, v.x, d);
    r.y = v.y + __shfl_xor_sync(0xffffffffu, v.y, d);
    r.z = v.z + __shfl_xor_sync(0xffffffffu, v.z, d);
    r.w = v.w + __shfl_xor_sync(0xffffffffu, v.w, d);
    return r;
}

__global__ void __launch_bounds__(512, 1) fused_kernel(
    const float* __restrict__ x,
    const float* __restrict__ w_diag,
    const float* __restrict__ w_off,
    const float* __restrict__ b1,
    const int*   __restrict__ perm,
    float*       __restrict__ out)
{
    // f4 union: Wp[0,544) Wm[544,1088) Sp[1088,1632) Sm[1632,2176); stage floats after
    __shared__ float4 SM4[2176];
    __shared__ float4 wdsh4[264];    // [(iq)*33 + o] : w_diag[(o*32+4iq..+3), k]
    __shared__ float4 tsh4[64];      // [p*32 + sL*8 + oq] : T[p][sL][o]
    __shared__ float  bsh[32];
    float* SMf  = (float*)SM4;
    float* tshF = (float*)tsh4;

    const int b = blockIdx.x, t = threadIdx.x;
    const int k = b >> 3, sg = b & 7;          // producer Bg == consumer sg

    if (t < 32) bsh[t] = __ldg(&b1[t]);

    // ---- finalize-role indices + x row prefetch (earliest possible) ----
    const int sL = t >> 7, aa = (t >> 3) & 15, og = t & 7;
    const int n2 = __ldg(&perm[k * 16 + aa]);
    float4 xr[8];
    {
        const float4* xrow = (const float4*)(x + (4 * sg + sL) * XS + n2 * 32);
#pragma unroll
        for (int iq = 0; iq < 8; iq++) xr[iq] = __ldg(&xrow[iq]);
    }

    // ---- W prefetch for contraction ----
    const float4* woff4 = (const float4*)w_off;     // [c][k][B/4]
    float4 wreg[2];
#pragma unroll
    for (int j = 0; j < 2; j++)
        wreg[j] = __ldg(&woff4[(j * 512 + t) * 128 + k * 8 + sg]);

    // ---- w_diag column k straight into smem (no global staging) ----
    {
        float* wdf = (float*)wdsh4;
#pragma unroll
        for (int j = 0; j < 2; j++) {
            int c = j * 512 + t;                    // c = o*32 + i
            int o = c >> 5, i = c & 31;
            wdf[((i >> 2) * 33 + o) * 4 + (i & 3)] = __ldg(&w_diag[c * 16 + k]);
        }
    }

    // ================= phase A: local gather + S± pooling ===================
    {
        const int sA = t >> 4, iqA = t & 7, rh = (t >> 3) & 1;
        const float4* x4 = (const float4*)x;
        float4 sB[4];
#pragma unroll
        for (int Bl = 0; Bl < 4; Bl++) {
            float4 a = make_float4(0.f, 0.f, 0.f, 0.f);
#pragma unroll
            for (int rr = 0; rr < 4; rr++) {
                int n = __ldg(&perm[sg * 32 + Bl * 8 + rh * 4 + rr]);
                float4 v = __ldg(&x4[sA * 2048 + n * 8 + iqA]);
                a.x += v.x; a.y += v.y; a.z += v.z; a.w += v.w;
            }
            sB[Bl] = a;
        }
#pragma unroll
        for (int Bl = 0; Bl < 4; Bl++) sB[Bl] = shfl_xor_add_f4(sB[Bl], 8);

        if (rh == 0) {   // Sp rows: [s*17 + m*8 + iq]
            float4 p0, p1;
            p0.x = sB[0].x + sB[1].x; p0.y = sB[0].y + sB[1].y;
            p0.z = sB[0].z + sB[1].z; p0.w = sB[0].w + sB[1].w;
            p1.x = sB[2].x + sB[3].x; p1.y = sB[2].y + sB[3].y;
            p1.z = sB[2].z + sB[3].z; p1.w = sB[2].w + sB[3].w;
            SM4[1088 + sA * 17 +     iqA] = p0;
            SM4[1088 + sA * 17 + 8 + iqA] = p1;
        } else {         // Sm rows
            float4 q0, q1;
            q0.x = sB[0].x - sB[1].x; q0.y = sB[0].y - sB[1].y;
            q0.z = sB[0].z - sB[1].z; q0.w = sB[0].w - sB[1].w;
            q1.x = sB[2].x - sB[3].x; q1.y = sB[2].y - sB[3].y;
            q1.z = sB[2].z - sB[3].z; q1.w = sB[2].w - sB[3].w;
            SM4[1632 + sA * 17 +     iqA] = q0;
            SM4[1632 + sA * 17 + 8 + iqA] = q1;
        }
    }

    // ---- W± -> smem ----
    {
        float* Wp = SMf;              // row o: 68 floats
        float* Wm = SMf + 544 * 4;
#pragma unroll
        for (int jj = 0; jj < 2; jj++) {
            int c = jj * 512 + t, o = c >> 5, i = c & 31;
            float4 w = wreg[jj];
            Wp[o * 68 +      i] = w.x + w.y;   // m=0
            Wp[o * 68 + 32 + i] = w.z + w.w;   // m=1
            Wm[o * 68 +      i] = w.x - w.y;
            Wm[o * 68 + 32 + i] = w.z - w.w;
        }
    }
    __syncthreads();

    // ================= phase B: contraction (all 512 threads) ===============
    float acc[4][4];
    {
        const int pq = t >> 8, sh = (t >> 5) & 7, ogB = (t >> 2) & 7, ih = t & 3;
        const float4* Wb = SM4 + (pq ? 544 : 0);
        const float4* Sb = SM4 + 1088 + (pq ? 544 : 0);
#pragma unroll
        for (int j = 0; j < 16; j++) ((float*)acc)[j] = 0.f;
#pragma unroll
        for (int m = 0; m < 2; m++)
#pragma unroll
            for (int j = 0; j < 2; j++) {
                int iq = ih * 2 + j;
                float4 s4[4], w4[4];
#pragma unroll
                for (int ss = 0; ss < 4; ss++)
                    s4[ss] = Sb[(sh + 8 * ss) * 17 + m * 8 + iq];
#pragma unroll
                for (int oo = 0; oo < 4; oo++)
                    w4[oo] = Wb[(ogB + 8 * oo) * 17 + m * 8 + iq];
#pragma unroll
                for (int ss = 0; ss < 4; ss++)
#pragma unroll
                    for (int oo = 0; oo < 4; oo++)
                        acc[ss][oo] += w4[oo].x * s4[ss].x + w4[oo].y * s4[ss].y
                                     + w4[oo].z * s4[ss].z + w4[oo].w * s4[ss].w;
            }
    }
    __syncthreads();
#pragma unroll
    for (int jj = 0; jj < 16; jj++)
        SMf[jj * 513 + t] = acc[jj >> 2][jj & 3];
    __syncthreads();
    // reduce over ih (4) and store Tpart: [k][Bg(=sg)][pq][s][o], coalesced over o
    {
        const int pq = t >> 8, sh = (t >> 5) & 7, oo2 = (t >> 3) & 3, ogr = t & 7;
        const int g = pq * 64 + sh * 8 + ogr;
        float* Tdst = g_Tpart + ((k * 8 + sg) * 2 + pq) * 1024;
#pragma unroll
        for (int ss = 0; ss < 4; ss++) {
            int j = ss * 4 + oo2;
            float v = SMf[j * 513 + g * 4 + 0] + SMf[j * 513 + g * 4 + 1]
                    + SMf[j * 513 + g * 4 + 2] + SMf[j * 513 + g * 4 + 3];
            Tdst[(sh + 8 * ss) * 32 + (ogr + 8 * oo2)] = v;
        }
    }
    __syncthreads();

    // ---- release our Tpart; overlap diag GEMM with other producers --------
    unsigned int tgt = 0;
    if (t == 0) {
        unsigned int my = atom_add_rel(&g_cnt[k], 1u);
        tgt = ((my >> 3) + 1u) << 3;       // 8 producers per k
    }

    float acc2[4];
#pragma unroll
    for (int oo = 0; oo < 4; oo++) acc2[oo] = bsh[og + 8 * oo];
#pragma unroll
    for (int iq = 0; iq < 8; iq++) {
        float4 xv = xr[iq];
#pragma unroll
        for (int oo = 0; oo < 4; oo++) {
            float4 wv = wdsh4[iq * 33 + og + 8 * oo];
            acc2[oo] += wv.x * xv.x + wv.y * xv.y + wv.z * xv.z + wv.w * xv.w;
        }
    }

    if (t == 0) { while (ld_acq(&g_cnt[k]) < tgt) {} }
    __syncthreads();

    // ---- T reduce (one warp, MLP 16): T[p][sL][o] = (P ± Q)/512 ------------
    if (t < 32) {
        int sL2 = t >> 3, oq = t & 7;
        const float4* Tp4 = (const float4*)g_Tpart;
        float4 P = make_float4(0.f, 0.f, 0.f, 0.f);
        float4 Q = make_float4(0.f, 0.f, 0.f, 0.f);
#pragma unroll
        for (int Bg = 0; Bg < 8; Bg++) {
            float4 vp = __ldcg(&Tp4[((k * 8 + Bg) * 2 + 0) * 256 + (4 * sg + sL2) * 8 + oq]);
            float4 vq = __ldcg(&Tp4[((k * 8 + Bg) * 2 + 1) * 256 + (4 * sg + sL2) * 8 + oq]);
            P.x += vp.x; P.y += vp.y; P.z += vp.z; P.w += vp.w;
            Q.x += vq.x; Q.y += vq.y; Q.z += vq.z; Q.w += vq.w;
        }
        const float c = 1.0f / 512.0f;
        float4 T0, T1;
        T0.x = (P.x + Q.x) * c; T0.y = (P.y + Q.y) * c;
        T0.z = (P.z + Q.z) * c; T0.w = (P.w + Q.w) * c;
        T1.x = (P.x - Q.x) * c; T1.y = (P.y - Q.y) * c;
        T1.z = (P.z - Q.z) * c; T1.w = (P.w - Q.w) * c;
        tsh4[     sL2 * 8 + oq] = T0;
        tsh4[32 + sL2 * 8 + oq] = T1;
    }
    __syncthreads();

    // ---- add T term + store -------------------------------------------------
    const int pa = aa >> 3;
    float* orow = out + (4 * sg + sL) * XS + n2 * 32;
#pragma unroll
    for (int oo = 0; oo < 4; oo++)
        orow[og + 8 * oo] = acc2[oo] + tshF[pa * 128 + sL * 32 + og + 8 * oo];
}

// ---------------------------------------------------------------------------
extern "C" void kernel_launch(void* const* d_in, const int* in_sizes, int n_in,
                              void* d_out, int out_size)
{
    const float* x      = (const float*)d_in[0];
    const float* w_diag = (const float*)d_in[1];
    const float* w_off  = (const float*)d_in[2];
    const float* b1     = (const float*)d_in[3];
    const int*   perm   = (const int*)d_in[4];
    float* out = (float*)d_out;

    fused_kernel<<<NBLK, 512>>>(x, w_diag, w_off, b1, perm, out);
}